// round 1
// baseline (speedup 1.0000x reference)
#include <cuda_runtime.h>
#include <cuda_bf16.h>

// ---------------- problem constants (fixed shapes per reference) -------------
#define NMAX   50000
#define EMAX   1250000
#define GMAX   1024
#define LD     32      // label/embedding dim
#define HD     64      // hidden dim

// ---------------- device scratch (no allocation allowed) --------------------
__device__ float g_h0 [NMAX * LD];   // embedded labels
__device__ float g_ag0[NMAX * LD];   // layer0 aggregation
__device__ float g_h1 [NMAX * HD];   // layer0 output h
__device__ float g_ag1[NMAX * HD];   // layer1 aggregation
__device__ float g_a  [NMAX * HD];   // MLP intermediate (relu(z@w1+b1))
__device__ float g_sum[GMAX * HD];   // per-graph feature sums
__device__ float g_cnt[GMAX];        // per-graph node counts

// ---------------- init: embedding lookup + zero all accumulators ------------
__global__ void init_kernel(const int* __restrict__ labels,
                            const float* __restrict__ emb,
                            int n, int g, int max_label,
                            float* __restrict__ h0, float* __restrict__ ag0,
                            float* __restrict__ ag1,
                            float* __restrict__ sums, float* __restrict__ cnts)
{
    int idx = blockIdx.x * blockDim.x + threadIdx.x;
    if (idx < n * LD) {
        int node = idx >> 5;           // /32
        int d    = idx & (LD - 1);
        int lab  = labels[node];
        lab = lab < 0 ? 0 : (lab > max_label ? max_label : lab);
        h0[idx]  = emb[lab * LD + d];
        ag0[idx] = 0.f;
    }
    if (idx < n * HD) ag1[idx] = 0.f;
    if (idx < g * HD) sums[idx] = 0.f;
    if (idx < g)      cnts[idx] = 0.f;
}

// ---------------- edge scatter: agg[dst] += h[src] (vector atomics) ---------
// DIM = feature dim (32 or 64); each thread moves one float4 of one edge.
template <int DIM>
__global__ void scatter_kernel(const int* __restrict__ src,
                               const int* __restrict__ dst,
                               const float* __restrict__ h,
                               float* __restrict__ agg, int E)
{
    const int J = DIM / 4;                       // float4 chunks per edge
    int idx = blockIdx.x * blockDim.x + threadIdx.x;
    if (idx >= E * J) return;
    int e = idx / J;
    int j = idx - e * J;
    int s = __ldg(&src[e]);
    int d = __ldg(&dst[e]);
    float4 v = *reinterpret_cast<const float4*>(h + (size_t)s * DIM + j * 4);
    atomicAdd(reinterpret_cast<float4*>(agg + (size_t)d * DIM + j * 4), v);
}

// ---------------- MLP half-layer: out = relu(bias + (x1[+x2]) @ W) ----------
// Node-per-thread; W (IN x 64, row-major) staged in shared memory;
// 64 fp32 accumulators in registers; inner f-loop fully unrolled.
template <int IN, bool ADD2>
__global__ void __launch_bounds__(128)
mlp_kernel(const float* __restrict__ x1, const float* __restrict__ x2,
           const float* __restrict__ W, const float* __restrict__ bias,
           float* __restrict__ out, int n)
{
    __shared__ float Wsm[IN * HD];
    __shared__ float bsm[HD];
    for (int i = threadIdx.x; i < IN * HD; i += blockDim.x) Wsm[i] = W[i];
    if (threadIdx.x < HD) bsm[threadIdx.x] = bias[threadIdx.x];
    __syncthreads();

    int node = blockIdx.x * blockDim.x + threadIdx.x;
    if (node >= n) return;

    float acc[HD];
#pragma unroll
    for (int f = 0; f < HD; f++) acc[f] = bsm[f];

    const float* r1 = x1 + (size_t)node * IN;
    const float* r2 = ADD2 ? (x2 + (size_t)node * IN) : nullptr;
    for (int k = 0; k < IN; k++) {
        float zk = r1[k];
        if (ADD2) zk += r2[k];
#pragma unroll
        for (int f = 0; f < HD; f++) acc[f] += zk * Wsm[k * HD + f];
    }

    float* o = out + (size_t)node * HD;
#pragma unroll
    for (int f = 0; f < HD; f++) o[f] = fmaxf(acc[f], 0.f);
}

// ---------------- final MLP half + fused mean-pool accumulation -------------
__global__ void __launch_bounds__(128)
mlp_pool_kernel(const float* __restrict__ x1,
                const float* __restrict__ W, const float* __restrict__ bias,
                const int* __restrict__ graph_ids,
                float* __restrict__ sums, float* __restrict__ cnts, int n)
{
    __shared__ float Wsm[HD * HD];
    __shared__ float bsm[HD];
    for (int i = threadIdx.x; i < HD * HD; i += blockDim.x) Wsm[i] = W[i];
    if (threadIdx.x < HD) bsm[threadIdx.x] = bias[threadIdx.x];
    __syncthreads();

    int node = blockIdx.x * blockDim.x + threadIdx.x;
    if (node >= n) return;

    float acc[HD];
#pragma unroll
    for (int f = 0; f < HD; f++) acc[f] = bsm[f];

    const float* r1 = x1 + (size_t)node * HD;
    for (int k = 0; k < HD; k++) {
        float zk = r1[k];
#pragma unroll
        for (int f = 0; f < HD; f++) acc[f] += zk * Wsm[k * HD + f];
    }

    int g = graph_ids[node];
    atomicAdd(&cnts[g], 1.0f);
    float* sg = sums + (size_t)g * HD;
#pragma unroll
    for (int f = 0; f < HD; f += 4) {
        float4 v = make_float4(fmaxf(acc[f + 0], 0.f), fmaxf(acc[f + 1], 0.f),
                               fmaxf(acc[f + 2], 0.f), fmaxf(acc[f + 3], 0.f));
        atomicAdd(reinterpret_cast<float4*>(sg + f), v);
    }
}

// ---------------- scorer: out[g] = relu(mean_h @ sw1 + sb1) @ sw2 + sb2 -----
__global__ void scorer_kernel(const float* __restrict__ sums,
                              const float* __restrict__ cnts,
                              const float* __restrict__ sw1,
                              const float* __restrict__ sb1,
                              const float* __restrict__ sw2,
                              const float* __restrict__ sb2,
                              float* __restrict__ out)
{
    int g = blockIdx.x;
    int f = threadIdx.x;           // 64 threads
    float cnt = fmaxf(cnts[g], 1.0f);
    float inv = 1.0f / cnt;
    float acc = sb1[f];
    const float* sg = sums + (size_t)g * HD;
    for (int k = 0; k < HD; k++) acc += (sg[k] * inv) * sw1[k * HD + f];
    float hf = fmaxf(acc, 0.f) * sw2[f];

    __shared__ float red[HD];
    red[f] = hf;
    __syncthreads();
    if (f < 32) red[f] += red[f + 32];
    __syncthreads();
    if (f < 32) {
        float v = red[f];
#pragma unroll
        for (int off = 16; off > 0; off >>= 1)
            v += __shfl_down_sync(0xFFFFFFFFu, v, off);
        if (f == 0) out[g] = v + sb2[0];
    }
}

// ---------------- launcher --------------------------------------------------
extern "C" void kernel_launch(void* const* d_in, const int* in_sizes, int n_in,
                              void* d_out, int out_size)
{
    const int*   labels = (const int*)  d_in[0];
    const int*   src    = (const int*)  d_in[1];
    const int*   dst    = (const int*)  d_in[2];
    const int*   gids   = (const int*)  d_in[3];
    const float* emb    = (const float*)d_in[4];
    const float* w1_0   = (const float*)d_in[5];
    const float* b1_0   = (const float*)d_in[6];
    const float* w2_0   = (const float*)d_in[7];
    const float* b2_0   = (const float*)d_in[8];
    const float* w1_1   = (const float*)d_in[9];
    const float* b1_1   = (const float*)d_in[10];
    const float* w2_1   = (const float*)d_in[11];
    const float* b2_1   = (const float*)d_in[12];
    const float* sw1    = (const float*)d_in[13];
    const float* sb1    = (const float*)d_in[14];
    const float* sw2    = (const float*)d_in[15];
    const float* sb2    = (const float*)d_in[16];
    float* out = (float*)d_out;

    int N = in_sizes[0];
    int E = in_sizes[1];
    int G = out_size;                         // [G,1] output
    int max_label = in_sizes[4] / LD - 1;     // emb rows - 1

    if (N > NMAX) N = NMAX;
    if (E > EMAX) E = EMAX;
    if (G > GMAX) G = GMAX;

    float *h0, *ag0, *h1, *ag1, *a, *sums, *cnts;
    cudaGetSymbolAddress((void**)&h0,   g_h0);
    cudaGetSymbolAddress((void**)&ag0,  g_ag0);
    cudaGetSymbolAddress((void**)&h1,   g_h1);
    cudaGetSymbolAddress((void**)&ag1,  g_ag1);
    cudaGetSymbolAddress((void**)&a,    g_a);
    cudaGetSymbolAddress((void**)&sums, g_sum);
    cudaGetSymbolAddress((void**)&cnts, g_cnt);

    const int TB = 256;
    // 1. embedding + zero accumulators
    init_kernel<<<(N * HD + TB - 1) / TB, TB>>>(labels, emb, N, G, max_label,
                                                h0, ag0, ag1, sums, cnts);
    // 2. layer0 scatter: ag0[dst] += h0[src]  (32-dim)
    scatter_kernel<LD><<<(E * (LD / 4) + TB - 1) / TB, TB>>>(src, dst, h0, ag0, E);
    // 3. layer0 MLP:  a = relu((h0+ag0) @ w1_0 + b1_0);  h1 = relu(a @ w2_0 + b2_0)
    mlp_kernel<LD, true ><<<(N + 127) / 128, 128>>>(h0, ag0, w1_0, b1_0, a,  N);
    mlp_kernel<HD, false><<<(N + 127) / 128, 128>>>(a,  nullptr, w2_0, b2_0, h1, N);
    // 4. layer1 scatter: ag1[dst] += h1[src]  (64-dim)
    scatter_kernel<HD><<<(E * (HD / 4) + TB - 1) / TB, TB>>>(src, dst, h1, ag1, E);
    // 5. layer1 MLP + fused mean-pool accumulation
    mlp_kernel<HD, true ><<<(N + 127) / 128, 128>>>(h1, ag1, w1_1, b1_1, a, N);
    mlp_pool_kernel<<<(N + 127) / 128, 128>>>(a, w2_1, b2_1, gids, sums, cnts, N);
    // 6. scorer
    scorer_kernel<<<G, HD>>>(sums, cnts, sw1, sb1, sw2, sb2, out);
}

// round 2
// speedup vs baseline: 1.3422x; 1.3422x over previous
#include <cuda_runtime.h>
#include <cuda_bf16.h>

// ---------------- problem constants (fixed shapes per reference) -------------
#define NMAX   50000
#define EMAX   1250000
#define GMAX   1024
#define LD     32      // label/embedding dim
#define HD     64      // hidden dim
#define FCH    32      // output-feature chunk per block (2 chunks cover HD)

// ---------------- device scratch (no allocation allowed) --------------------
__device__ float g_h0 [NMAX * LD];   // embedded labels
__device__ float g_ag0[NMAX * LD];   // layer0 aggregation
__device__ float g_h1 [NMAX * HD];   // layer0 output h
__device__ float g_ag1[NMAX * HD];   // layer1 aggregation
__device__ float g_a  [NMAX * HD];   // MLP intermediate (relu(z@w1+b1))
__device__ float g_sum[GMAX * HD];   // per-graph feature sums
__device__ float g_cnt[GMAX];        // per-graph node counts

// ---------------- init: embedding lookup + zero all accumulators ------------
__global__ void init_kernel(const int* __restrict__ labels,
                            const float* __restrict__ emb,
                            int n, int g, int max_label,
                            float* __restrict__ h0, float* __restrict__ ag0,
                            float* __restrict__ ag1,
                            float* __restrict__ sums, float* __restrict__ cnts)
{
    int idx = blockIdx.x * blockDim.x + threadIdx.x;
    if (idx < n * LD) {
        int node = idx >> 5;           // /32
        int d    = idx & (LD - 1);
        int lab  = labels[node];
        lab = lab < 0 ? 0 : (lab > max_label ? max_label : lab);
        h0[idx]  = emb[lab * LD + d];
        ag0[idx] = 0.f;
    }
    if (idx < n * HD) ag1[idx] = 0.f;
    if (idx < g * HD) sums[idx] = 0.f;
    if (idx < g)      cnts[idx] = 0.f;
}

// ---------------- edge scatter: agg[dst] += h[src] (vector atomics) ---------
template <int DIM>
__global__ void scatter_kernel(const int* __restrict__ src,
                               const int* __restrict__ dst,
                               const float* __restrict__ h,
                               float* __restrict__ agg, int E)
{
    const int J = DIM / 4;                       // float4 chunks per edge
    int idx = blockIdx.x * blockDim.x + threadIdx.x;
    if (idx >= E * J) return;
    int e = idx / J;
    int j = idx - e * J;
    int s = __ldg(&src[e]);
    int d = __ldg(&dst[e]);
    float4 v = *reinterpret_cast<const float4*>(h + (size_t)s * DIM + j * 4);
    atomicAdd(reinterpret_cast<float4*>(agg + (size_t)d * DIM + j * 4), v);
}

// ---------------- MLP half-layer, 32-feature chunk per block ----------------
// out[:, FOFF:FOFF+32] = relu(bias + (x1[+x2]) @ W[:, FOFF:FOFF+32])
// Thread per node, 32 fp32 accumulators (no spills), W slice in shared.
template <int IN, bool ADD2>
__global__ void __launch_bounds__(256)
mlp_kernel(const float* __restrict__ x1, const float* __restrict__ x2,
           const float* __restrict__ W, const float* __restrict__ bias,
           float* __restrict__ out, int n)
{
    const int FOFF = blockIdx.y * FCH;
    __shared__ float Wsm[IN * FCH];
    __shared__ float bsm[FCH];
    for (int i = threadIdx.x; i < IN * FCH; i += blockDim.x) {
        int k = i / FCH, f = i % FCH;
        Wsm[i] = W[k * HD + FOFF + f];
    }
    if (threadIdx.x < FCH) bsm[threadIdx.x] = bias[FOFF + threadIdx.x];
    __syncthreads();

    int node = blockIdx.x * blockDim.x + threadIdx.x;
    if (node >= n) return;

    float acc[FCH];
#pragma unroll
    for (int f = 0; f < FCH; f++) acc[f] = bsm[f];

    const float4* r1 = reinterpret_cast<const float4*>(x1 + (size_t)node * IN);
    const float4* r2 = ADD2 ? reinterpret_cast<const float4*>(x2 + (size_t)node * IN)
                            : nullptr;
#pragma unroll
    for (int k4 = 0; k4 < IN / 4; k4++) {
        float4 xa = r1[k4];
        if (ADD2) {
            float4 xb = r2[k4];
            xa.x += xb.x; xa.y += xb.y; xa.z += xb.z; xa.w += xb.w;
        }
        const float zk[4] = {xa.x, xa.y, xa.z, xa.w};
#pragma unroll
        for (int kk = 0; kk < 4; kk++) {
            const float4* wrow = reinterpret_cast<const float4*>(Wsm + (k4 * 4 + kk) * FCH);
#pragma unroll
            for (int f4 = 0; f4 < FCH / 4; f4++) {
                float4 w = wrow[f4];
                acc[f4 * 4 + 0] += zk[kk] * w.x;
                acc[f4 * 4 + 1] += zk[kk] * w.y;
                acc[f4 * 4 + 2] += zk[kk] * w.z;
                acc[f4 * 4 + 3] += zk[kk] * w.w;
            }
        }
    }

    float4* o = reinterpret_cast<float4*>(out + (size_t)node * HD + FOFF);
#pragma unroll
    for (int f4 = 0; f4 < FCH / 4; f4++) {
        o[f4] = make_float4(fmaxf(acc[f4 * 4 + 0], 0.f), fmaxf(acc[f4 * 4 + 1], 0.f),
                            fmaxf(acc[f4 * 4 + 2], 0.f), fmaxf(acc[f4 * 4 + 3], 0.f));
    }
}

// ---------------- final MLP half + fused mean-pool accumulation -------------
__global__ void __launch_bounds__(256)
mlp_pool_kernel(const float* __restrict__ x1,
                const float* __restrict__ W, const float* __restrict__ bias,
                const int* __restrict__ graph_ids,
                float* __restrict__ sums, float* __restrict__ cnts, int n)
{
    const int FOFF = blockIdx.y * FCH;
    __shared__ float Wsm[HD * FCH];
    __shared__ float bsm[FCH];
    for (int i = threadIdx.x; i < HD * FCH; i += blockDim.x) {
        int k = i / FCH, f = i % FCH;
        Wsm[i] = W[k * HD + FOFF + f];
    }
    if (threadIdx.x < FCH) bsm[threadIdx.x] = bias[FOFF + threadIdx.x];
    __syncthreads();

    int node = blockIdx.x * blockDim.x + threadIdx.x;
    if (node >= n) return;

    float acc[FCH];
#pragma unroll
    for (int f = 0; f < FCH; f++) acc[f] = bsm[f];

    const float4* r1 = reinterpret_cast<const float4*>(x1 + (size_t)node * HD);
#pragma unroll
    for (int k4 = 0; k4 < HD / 4; k4++) {
        float4 xa = r1[k4];
        const float zk[4] = {xa.x, xa.y, xa.z, xa.w};
#pragma unroll
        for (int kk = 0; kk < 4; kk++) {
            const float4* wrow = reinterpret_cast<const float4*>(Wsm + (k4 * 4 + kk) * FCH);
#pragma unroll
            for (int f4 = 0; f4 < FCH / 4; f4++) {
                float4 w = wrow[f4];
                acc[f4 * 4 + 0] += zk[kk] * w.x;
                acc[f4 * 4 + 1] += zk[kk] * w.y;
                acc[f4 * 4 + 2] += zk[kk] * w.z;
                acc[f4 * 4 + 3] += zk[kk] * w.w;
            }
        }
    }

    int g = graph_ids[node];
    if (blockIdx.y == 0) atomicAdd(&cnts[g], 1.0f);
    float* sg = sums + (size_t)g * HD + FOFF;
#pragma unroll
    for (int f = 0; f < FCH; f += 4) {
        float4 v = make_float4(fmaxf(acc[f + 0], 0.f), fmaxf(acc[f + 1], 0.f),
                               fmaxf(acc[f + 2], 0.f), fmaxf(acc[f + 3], 0.f));
        atomicAdd(reinterpret_cast<float4*>(sg + f), v);
    }
}

// ---------------- scorer: out[g] = relu(mean_h @ sw1 + sb1) @ sw2 + sb2 -----
__global__ void scorer_kernel(const float* __restrict__ sums,
                              const float* __restrict__ cnts,
                              const float* __restrict__ sw1,
                              const float* __restrict__ sb1,
                              const float* __restrict__ sw2,
                              const float* __restrict__ sb2,
                              float* __restrict__ out)
{
    int g = blockIdx.x;
    int f = threadIdx.x;           // 64 threads
    float cnt = fmaxf(cnts[g], 1.0f);
    float inv = 1.0f / cnt;
    float acc = sb1[f];
    const float* sg = sums + (size_t)g * HD;
    for (int k = 0; k < HD; k++) acc += (sg[k] * inv) * sw1[k * HD + f];
    float hf = fmaxf(acc, 0.f) * sw2[f];

    __shared__ float red[HD];
    red[f] = hf;
    __syncthreads();
    if (f < 32) red[f] += red[f + 32];
    __syncthreads();
    if (f < 32) {
        float v = red[f];
#pragma unroll
        for (int off = 16; off > 0; off >>= 1)
            v += __shfl_down_sync(0xFFFFFFFFu, v, off);
        if (f == 0) out[g] = v + sb2[0];
    }
}

// ---------------- launcher --------------------------------------------------
extern "C" void kernel_launch(void* const* d_in, const int* in_sizes, int n_in,
                              void* d_out, int out_size)
{
    const int*   labels = (const int*)  d_in[0];
    const int*   src    = (const int*)  d_in[1];
    const int*   dst    = (const int*)  d_in[2];
    const int*   gids   = (const int*)  d_in[3];
    const float* emb    = (const float*)d_in[4];
    const float* w1_0   = (const float*)d_in[5];
    const float* b1_0   = (const float*)d_in[6];
    const float* w2_0   = (const float*)d_in[7];
    const float* b2_0   = (const float*)d_in[8];
    const float* w1_1   = (const float*)d_in[9];
    const float* b1_1   = (const float*)d_in[10];
    const float* w2_1   = (const float*)d_in[11];
    const float* b2_1   = (const float*)d_in[12];
    const float* sw1    = (const float*)d_in[13];
    const float* sb1    = (const float*)d_in[14];
    const float* sw2    = (const float*)d_in[15];
    const float* sb2    = (const float*)d_in[16];
    float* out = (float*)d_out;

    int N = in_sizes[0];
    int E = in_sizes[1];
    int G = out_size;                         // [G,1] output
    int max_label = in_sizes[4] / LD - 1;     // emb rows - 1

    if (N > NMAX) N = NMAX;
    if (E > EMAX) E = EMAX;
    if (G > GMAX) G = GMAX;

    float *h0, *ag0, *h1, *ag1, *a, *sums, *cnts;
    cudaGetSymbolAddress((void**)&h0,   g_h0);
    cudaGetSymbolAddress((void**)&ag0,  g_ag0);
    cudaGetSymbolAddress((void**)&h1,   g_h1);
    cudaGetSymbolAddress((void**)&ag1,  g_ag1);
    cudaGetSymbolAddress((void**)&a,    g_a);
    cudaGetSymbolAddress((void**)&sums, g_sum);
    cudaGetSymbolAddress((void**)&cnts, g_cnt);

    const int TB = 256;
    dim3 mgrid((N + 255) / 256, HD / FCH);    // 2 feature chunks

    // 1. embedding + zero accumulators
    init_kernel<<<(N * HD + TB - 1) / TB, TB>>>(labels, emb, N, G, max_label,
                                                h0, ag0, ag1, sums, cnts);
    // 2. layer0 scatter: ag0[dst] += h0[src]  (32-dim)
    scatter_kernel<LD><<<(E * (LD / 4) + TB - 1) / TB, TB>>>(src, dst, h0, ag0, E);
    // 3. layer0 MLP:  a = relu((h0+ag0) @ w1_0 + b1_0);  h1 = relu(a @ w2_0 + b2_0)
    mlp_kernel<LD, true ><<<mgrid, 256>>>(h0, ag0, w1_0, b1_0, a,  N);
    mlp_kernel<HD, false><<<mgrid, 256>>>(a,  nullptr, w2_0, b2_0, h1, N);
    // 4. layer1 scatter: ag1[dst] += h1[src]  (64-dim)
    scatter_kernel<HD><<<(E * (HD / 4) + TB - 1) / TB, TB>>>(src, dst, h1, ag1, E);
    // 5. layer1 MLP + fused mean-pool accumulation
    mlp_kernel<HD, true ><<<mgrid, 256>>>(h1, ag1, w1_1, b1_1, a, N);
    mlp_pool_kernel<<<mgrid, 256>>>(a, w2_1, b2_1, gids, sums, cnts, N);
    // 6. scorer
    scorer_kernel<<<G, HD>>>(sums, cnts, sw1, sb1, sw2, sb2, out);
}

// round 4
// speedup vs baseline: 1.5815x; 1.1783x over previous
#include <cuda_runtime.h>
#include <cuda_bf16.h>

// ---------------- problem constants (fixed shapes per reference) -------------
#define NMAX   50000
#define EMAX   1250000
#define GMAX   1024
#define LD     32      // label/embedding dim
#define HD     64      // hidden dim

// ---------------- device scratch (no allocation allowed) --------------------
__device__ float g_h0 [NMAX * LD];   // embedded labels
__device__ float g_ag0[NMAX * LD];   // layer0 aggregation
__device__ float g_h1 [NMAX * HD];   // layer0 output h
__device__ float g_ag1[NMAX * HD];   // layer1 aggregation
__device__ float g_a  [NMAX * HD];   // MLP intermediate
__device__ float g_sum[GMAX * HD];   // per-graph feature sums
__device__ float g_cnt[GMAX];        // per-graph node counts

// ---------------- init: embedding lookup + zero all accumulators ------------
__global__ void init_kernel(const int* __restrict__ labels,
                            const float* __restrict__ emb,
                            int n, int g, int max_label,
                            float* __restrict__ h0, float* __restrict__ ag0,
                            float* __restrict__ ag1,
                            float* __restrict__ sums, float* __restrict__ cnts)
{
    int idx = blockIdx.x * blockDim.x + threadIdx.x;
    if (idx < n * LD) {
        int node = idx >> 5;
        int d    = idx & (LD - 1);
        int lab  = labels[node];
        lab = lab < 0 ? 0 : (lab > max_label ? max_label : lab);
        h0[idx]  = emb[lab * LD + d];
        ag0[idx] = 0.f;
    }
    if (idx < n * HD) ag1[idx] = 0.f;
    if (idx < g * HD) sums[idx] = 0.f;
    if (idx < g)      cnts[idx] = 0.f;
}

// ---------------- edge scatter: agg[dst] += h[src] (vector atomics) ---------
template <int DIM>
__global__ void scatter_kernel(const int* __restrict__ src,
                               const int* __restrict__ dst,
                               const float* __restrict__ h,
                               float* __restrict__ agg, int E)
{
    const int J = DIM / 4;
    int idx = blockIdx.x * blockDim.x + threadIdx.x;
    if (idx >= E * J) return;
    int e = idx / J;
    int j = idx - e * J;
    int s = __ldg(&src[e]);
    int d = __ldg(&dst[e]);
    float4 v = *reinterpret_cast<const float4*>(h + (size_t)s * DIM + j * 4);
    atomicAdd(reinterpret_cast<float4*>(agg + (size_t)d * DIM + j * 4), v);
}

// ---------------- register-tiled GEMM half-layer ----------------------------
// out[64-node tile, 64 feats] = relu(bias + (x1[+x2]) @ W)  (W: [K][64] row-major)
// 128 threads; thread = 4 nodes x 8 features (32 fp32 accumulators).
// Xs staged transposed [K][64] with 68-float row pitch (conflict-free transpose).
// POOL variant: instead of writing out, atomically accumulate relu result into
// per-graph sums (+ node counts).
template <int K, bool ADD2, bool POOL>
__global__ void __launch_bounds__(128)
gemm_kernel(const float* __restrict__ x1, const float* __restrict__ x2,
            const float* __restrict__ W, const float* __restrict__ bias,
            float* __restrict__ out,
            const int* __restrict__ gids,
            float* __restrict__ sums, float* __restrict__ cnts, int n)
{
    const int XP = 68;                      // padded row pitch for Xs
    __shared__ float Xs[K * XP];            // [k][node]
    __shared__ float Ws[K * HD];            // [k][feat]
    __shared__ float bs[HD];

    const int tid = threadIdx.x;
    const int node_base = blockIdx.x * 64;

    // stage W (same layout as global: [K][64])
    {
        const float4* Wg = reinterpret_cast<const float4*>(W);
        float4* Wsm4 = reinterpret_cast<float4*>(Ws);
#pragma unroll
        for (int i = tid; i < K * HD / 4; i += 128) Wsm4[i] = Wg[i];
    }
    if (tid < HD) bs[tid] = bias[tid];

    // stage X transposed: Xs[k][n] = x1[node_base+n][k] (+ x2)
#pragma unroll
    for (int i = tid; i < 64 * (K / 4); i += 128) {
        int nn = i & 63;
        int kc = i >> 6;
        int node = node_base + nn;
        float4 v = make_float4(0.f, 0.f, 0.f, 0.f);
        if (node < n) {
            v = *reinterpret_cast<const float4*>(x1 + (size_t)node * K + kc * 4);
            if (ADD2) {
                float4 u = *reinterpret_cast<const float4*>(x2 + (size_t)node * K + kc * 4);
                v.x += u.x; v.y += u.y; v.z += u.z; v.w += u.w;
            }
        }
        Xs[(kc * 4 + 0) * XP + nn] = v.x;
        Xs[(kc * 4 + 1) * XP + nn] = v.y;
        Xs[(kc * 4 + 2) * XP + nn] = v.z;
        Xs[(kc * 4 + 3) * XP + nn] = v.w;
    }
    __syncthreads();

    const int tn = tid & 15;       // node group: 4 nodes each
    const int tf = tid >> 4;       // feature group: 8 feats each

    float acc[4][8];
#pragma unroll
    for (int i = 0; i < 4; i++)
#pragma unroll
        for (int j = 0; j < 8; j++) acc[i][j] = bs[tf * 8 + j];

#pragma unroll 8
    for (int k = 0; k < K; k++) {
        float4 xv = *reinterpret_cast<const float4*>(Xs + k * XP + tn * 4);
        float4 wa = *reinterpret_cast<const float4*>(Ws + k * HD + tf * 8);
        float4 wb = *reinterpret_cast<const float4*>(Ws + k * HD + tf * 8 + 4);
        const float xs[4] = {xv.x, xv.y, xv.z, xv.w};
        const float ws[8] = {wa.x, wa.y, wa.z, wa.w, wb.x, wb.y, wb.z, wb.w};
#pragma unroll
        for (int i = 0; i < 4; i++)
#pragma unroll
            for (int j = 0; j < 8; j++) acc[i][j] += xs[i] * ws[j];
    }

    // epilogue
#pragma unroll
    for (int i = 0; i < 4; i++) {
        int node = node_base + tn * 4 + i;
        if (node >= n) continue;
        float4 ra = make_float4(fmaxf(acc[i][0], 0.f), fmaxf(acc[i][1], 0.f),
                                fmaxf(acc[i][2], 0.f), fmaxf(acc[i][3], 0.f));
        float4 rb = make_float4(fmaxf(acc[i][4], 0.f), fmaxf(acc[i][5], 0.f),
                                fmaxf(acc[i][6], 0.f), fmaxf(acc[i][7], 0.f));
        if (!POOL) {
            float* o = out + (size_t)node * HD + tf * 8;
            *reinterpret_cast<float4*>(o)     = ra;
            *reinterpret_cast<float4*>(o + 4) = rb;
        } else {
            int g = gids[node];
            float* sg = sums + (size_t)g * HD + tf * 8;
            atomicAdd(reinterpret_cast<float4*>(sg),     ra);
            atomicAdd(reinterpret_cast<float4*>(sg + 4), rb);
            if (tf == 0) atomicAdd(&cnts[g], 1.0f);
        }
    }
}

// ---------------- scorer: out[g] = relu(mean_h @ sw1 + sb1) @ sw2 + sb2 -----
__global__ void scorer_kernel(const float* __restrict__ sums,
                              const float* __restrict__ cnts,
                              const float* __restrict__ sw1,
                              const float* __restrict__ sb1,
                              const float* __restrict__ sw2,
                              const float* __restrict__ sb2,
                              float* __restrict__ out)
{
    int g = blockIdx.x;
    int f = threadIdx.x;           // 64 threads
    float cnt = fmaxf(cnts[g], 1.0f);
    float inv = 1.0f / cnt;
    float acc = sb1[f];
    const float* sg = sums + (size_t)g * HD;
    for (int k = 0; k < HD; k++) acc += (sg[k] * inv) * sw1[k * HD + f];
    float hf = fmaxf(acc, 0.f) * sw2[f];

    __shared__ float red[HD];
    red[f] = hf;
    __syncthreads();
    if (f < 32) red[f] += red[f + 32];
    __syncthreads();
    if (f < 32) {
        float v = red[f];
#pragma unroll
        for (int off = 16; off > 0; off >>= 1)
            v += __shfl_down_sync(0xFFFFFFFFu, v, off);
        if (f == 0) out[g] = v + sb2[0];
    }
}

// ---------------- launcher --------------------------------------------------
extern "C" void kernel_launch(void* const* d_in, const int* in_sizes, int n_in,
                              void* d_out, int out_size)
{
    const int*   labels = (const int*)  d_in[0];
    const int*   src    = (const int*)  d_in[1];
    const int*   dst    = (const int*)  d_in[2];
    const int*   gids   = (const int*)  d_in[3];
    const float* emb    = (const float*)d_in[4];
    const float* w1_0   = (const float*)d_in[5];
    const float* b1_0   = (const float*)d_in[6];
    const float* w2_0   = (const float*)d_in[7];
    const float* b2_0   = (const float*)d_in[8];
    const float* w1_1   = (const float*)d_in[9];
    const float* b1_1   = (const float*)d_in[10];
    const float* w2_1   = (const float*)d_in[11];
    const float* b2_1   = (const float*)d_in[12];
    const float* sw1    = (const float*)d_in[13];
    const float* sb1    = (const float*)d_in[14];
    const float* sw2    = (const float*)d_in[15];
    const float* sb2    = (const float*)d_in[16];
    float* out = (float*)d_out;

    int N = in_sizes[0];
    int E = in_sizes[1];
    int G = out_size;
    int max_label = in_sizes[4] / LD - 1;

    if (N > NMAX) N = NMAX;
    if (E > EMAX) E = EMAX;
    if (G > GMAX) G = GMAX;

    float *h0, *ag0, *h1, *ag1, *a, *sums, *cnts;
    cudaGetSymbolAddress((void**)&h0,   g_h0);
    cudaGetSymbolAddress((void**)&ag0,  g_ag0);
    cudaGetSymbolAddress((void**)&h1,   g_h1);
    cudaGetSymbolAddress((void**)&ag1,  g_ag1);
    cudaGetSymbolAddress((void**)&a,    g_a);
    cudaGetSymbolAddress((void**)&sums, g_sum);
    cudaGetSymbolAddress((void**)&cnts, g_cnt);

    const int TB = 256;
    const int NB = (N + 63) / 64;    // node tiles

    // 1. embedding + zero accumulators
    init_kernel<<<(N * HD + TB - 1) / TB, TB>>>(labels, emb, N, G, max_label,
                                                h0, ag0, ag1, sums, cnts);
    // 2. layer0 scatter: ag0[dst] += h0[src]  (32-dim)
    scatter_kernel<LD><<<(E * (LD / 4) + TB - 1) / TB, TB>>>(src, dst, h0, ag0, E);
    // 3. layer0 MLP
    gemm_kernel<LD, true , false><<<NB, 128>>>(h0, ag0, w1_0, b1_0, a,  nullptr, nullptr, nullptr, N);
    gemm_kernel<HD, false, false><<<NB, 128>>>(a,  nullptr, w2_0, b2_0, h1, nullptr, nullptr, nullptr, N);
    // 4. layer1 scatter: ag1[dst] += h1[src]  (64-dim)
    scatter_kernel<HD><<<(E * (HD / 4) + TB - 1) / TB, TB>>>(src, dst, h1, ag1, E);
    // 5. layer1 MLP + fused mean-pool accumulation
    gemm_kernel<HD, true , false><<<NB, 128>>>(h1, ag1, w1_1, b1_1, a, nullptr, nullptr, nullptr, N);
    gemm_kernel<HD, false, true ><<<NB, 128>>>(a,  nullptr, w2_1, b2_1, nullptr, gids, sums, cnts, N);
    // 6. scorer
    scorer_kernel<<<G, HD>>>(sums, cnts, sw1, sb1, sw2, sb2, out);
}